// round 13
// baseline (speedup 1.0000x reference)
#include <cuda_runtime.h>
#include <cstdint>

// RBM block-Gibbs chain (CUDA-core path; tcgen05 unavailable: harness targets sm_103).
//
// R12 (9.48ms, rel_err 0.0): quad-sum table + smem nib exchange + PRMT + 5-FMA
// Taylor sigmoid. Pipes: L1 70.5 / alu 65.6 / issue 74.5 -> overlap-limited.
// R13: hand-pipeline each step. Uniforms are z-independent, so each of the 4
// threefry calls runs inside the L1-hit latency shadow of a batch of 8 table LDGs.
// Summation order, PRNG, sigmoid, compare: byte-identical to R12 (rel_err 0.0).

#define NSAMP    524288
#define LATENT   128
#define NSTEPS   30
#define WARPS_PB 8
#define THREADS_PB 256
#define NBLOCKS  (NSAMP / WARPS_PB)     // 65536

#define TAB_ELEMS (32 * 16 * 128)       // 256 KB fp32
__device__ __align__(256) float g_qtable[TAB_ELEMS];

struct Keys { uint2 k[1 + NSTEPS]; };   // k[0] = z0 key, k[1+t] = step t key

__host__ __device__ __forceinline__ uint32_t rotl32(uint32_t x, int r) {
#ifdef __CUDA_ARCH__
    return __funnelshift_l(x, x, r);
#else
    return (x << r) | (x >> (32 - r));
#endif
}

// Threefry-2x32, 20 rounds (exactly JAX's threefry2x32).
__host__ __device__ __forceinline__ uint2 tf2x32(uint32_t k0, uint32_t k1,
                                                 uint32_t x0, uint32_t x1) {
    uint32_t k2 = k0 ^ k1 ^ 0x1BD11BDAu;
    x0 += k0; x1 += k1;
#define TFR(r) { x0 += x1; x1 = rotl32(x1, r); x1 ^= x0; }
    TFR(13) TFR(15) TFR(26) TFR(6)   x0 += k1; x1 += k2 + 1u;
    TFR(17) TFR(29) TFR(16) TFR(24)  x0 += k2; x1 += k0 + 2u;
    TFR(13) TFR(15) TFR(26) TFR(6)   x0 += k0; x1 += k1 + 3u;
    TFR(17) TFR(29) TFR(16) TFR(24)  x0 += k1; x1 += k2 + 4u;
    TFR(13) TFR(15) TFR(26) TFR(6)   x0 += k2; x1 += k0 + 5u;
#undef TFR
    return make_uint2(x0, x1);
}

// Partitionable-mode random bits: counter = (hi=0, lo=flat_index), xor lanes.
__device__ __forceinline__ uint32_t tf_bits(uint32_t k0, uint32_t k1, uint32_t ctr) {
    uint2 r = tf2x32(k0, k1, 0u, ctr);
    return r.x ^ r.y;
}

// Packed fp32 pair add (elementwise RN; base Blackwell ISA, fma pipe).
__device__ __forceinline__ uint64_t add2(uint64_t a, uint64_t b) {
    uint64_t r; asm("add.rn.f32x2 %0, %1, %2;" : "=l"(r) : "l"(a), "l"(b)); return r;
}
__device__ __forceinline__ uint64_t pack2(float a, float b) {
    uint64_t r; asm("mov.b64 %0, {%1, %2};" : "=l"(r) : "f"(a), "f"(b)); return r;
}
__device__ __forceinline__ float2 unpack2(uint64_t v) {
    float2 r; asm("mov.b64 {%0, %1}, %2;" : "=f"(r.x), "=f"(r.y) : "l"(v)); return r;
}

// ---- build the quad table: T[q][i][j] = sum_{b ascending, bit b of i} W[4q+b][j] ----
__global__ void build_qtable_kernel(const float* __restrict__ W) {
    int t = blockIdx.x * blockDim.x + threadIdx.x;   // 0 .. 65535
    int j = t & 127;
    int i = (t >> 7) & 15;
    int q = t >> 11;
    float acc = 0.0f;
#pragma unroll
    for (int b = 0; b < 4; b++)
        if ((i >> b) & 1) acc += W[(4 * q + b) * 128 + j];
    g_qtable[t] = acc;
}

// ---- main chain kernel: one sample per warp ----
__global__ __launch_bounds__(THREADS_PB)
void rbm_gibbs_kernel(const float* __restrict__ hvec,
                      float* __restrict__ out,
                      Keys keys) {
    // Double-buffered per-warp nib strips: step t writes/reads buffer (t & 1).
    __shared__ __align__(16) uint8_t nibbuf[WARPS_PB][2][32];

    const int lane = threadIdx.x & 31;
    const int wid  = threadIdx.x >> 5;
    const int sample = blockIdx.x * WARPS_PB + wid;
    const uint32_t base = (uint32_t)sample * (uint32_t)LATENT + (uint32_t)(lane * 4);

    const float4 h4 = reinterpret_cast<const float4*>(hvec)[lane];
    const uint64_t h01 = pack2(h4.x, h4.y);
    const uint64_t h23 = pack2(h4.z, h4.w);

    // Table rows as packed pairs: row (q, idx) = 32 ulonglong2; lane reads entry 'lane'.
    const ulonglong2* __restrict__ tab =
        reinterpret_cast<const ulonglong2*>(g_qtable) + lane;

    // nib = this lane's quad index: bit c = z_{4*lane+c}
    uint32_t nib;
    {
        const uint32_t ik0 = keys.k[0].x, ik1 = keys.k[0].y;
        nib = 0u;
#pragma unroll
        for (int c = 0; c < 4; c++)
            nib |= (tf_bits(ik0, ik1, base + (uint32_t)c) & 1u) << c;
    }

    for (int t = 0; t < NSTEPS; t++) {
        // ---- warp-wide nib exchange: 1 STS + 2 broadcast LDS.128, one sync ----
        uint8_t* buf = nibbuf[wid][t & 1];
        buf[lane] = (uint8_t)nib;
        __syncwarp();
        const uint4 n0 = *reinterpret_cast<const uint4*>(&buf[0]);   // nibs 0..15
        const uint4 n1 = *reinterpret_cast<const uint4*>(&buf[16]);  // nibs 16..31
        const uint32_t r[8] = { n0.x, n0.y, n0.z, n0.w, n1.x, n1.y, n1.z, n1.w };

        const uint32_t sk0 = keys.k[1 + t].x, sk1 = keys.k[1 + t].y;

        uint64_t y01 = h01, y23 = h23;
        float u[4];

        // 4 batches: issue 8 table LDGs, run one threefry (z-independent) in the
        // load shadow, then consume. Consumption order stays ascending-q, so the
        // summation is bit-identical to R12.
#pragma unroll
        for (int b = 0; b < 4; b++) {
            uint64_t wx[8], wy[8];
#pragma unroll
            for (int i = 0; i < 8; i++) {
                const int q = b * 8 + i;
                uint32_t nb = __byte_perm(r[q >> 2], 0u, 0x4440u | (uint32_t)(q & 3));
                ulonglong2 w = __ldg(&tab[(uint32_t)(q * 512) + nb * 32u]);
                wx[i] = w.x; wy[i] = w.y;
            }
            // threefry for this step's uniform c=b, overlapped with the 8 loads
            uint32_t bb = tf_bits(sk0, sk1, base + (uint32_t)b);
            u[b] = __uint_as_float((bb >> 9) | 0x3f800000u) - 1.0f;
#pragma unroll
            for (int i = 0; i < 8; i++) {
                y01 = add2(y01, wx[i]);
                y23 = add2(y23, wy[i]);
            }
        }

        // sample: z' = (u < sigmoid(y)); sigmoid via odd Taylor poly (|y| <= ~0.10,
        // analytic err < 2e-14, byte-identical to R12).
        float2 ya = unpack2(y01);
        float2 yc = unpack2(y23);
        float yv[4] = { ya.x, ya.y, yc.x, yc.y };
        nib = 0u;
#pragma unroll
        for (int c = 0; c < 4; c++) {
            float y2 = yv[c] * yv[c];
            float poly = fmaf(y2, fmaf(y2, fmaf(y2, -2.1081349e-4f, 2.0833333e-3f),
                                       -2.0833333e-2f), 0.25f);
            float p = fmaf(yv[c], poly, 0.5f);
            nib |= (u[c] < p ? 1u : 0u) << c;
        }
    }

    // ---- write z_final (float32, row-major [NSAMP, 128]) ----
    float4 v = make_float4((nib & 1u) ? 1.0f : 0.0f,
                           (nib & 2u) ? 1.0f : 0.0f,
                           (nib & 4u) ? 1.0f : 0.0f,
                           (nib & 8u) ? 1.0f : 0.0f);
    reinterpret_cast<float4*>(out)[(size_t)sample * 32 + lane] = v;
}

extern "C" void kernel_launch(void* const* d_in, const int* in_sizes, int n_in,
                              void* d_out, int out_size) {
    (void)in_sizes; (void)n_in; (void)out_size;
    const float* h = (const float*)d_in[0];
    const float* W = (const float*)d_in[1];
    float* out = (float*)d_out;

    // Host-side key schedule (pure CPU math; deterministic, capture-safe).
    Keys keys;
    uint2 kinit = tf2x32(0u, 42u, 0u, 0u);
    uint2 kloop = tf2x32(0u, 42u, 0u, 1u);
    keys.k[0] = kinit;
    for (int t = 0; t < NSTEPS; t++)
        keys.k[1 + t] = tf2x32(kloop.x, kloop.y, 0u, (uint32_t)t);

    // Same stream: table build completes before the chain kernel reads it.
    build_qtable_kernel<<<TAB_ELEMS / 256, 256>>>(W);
    rbm_gibbs_kernel<<<NBLOCKS, THREADS_PB>>>(h, out, keys);
}

// round 14
// speedup vs baseline: 1.0724x; 1.0724x over previous
#include <cuda_runtime.h>
#include <cstdint>

// RBM block-Gibbs chain (CUDA-core path; tcgen05 unavailable: harness targets sm_103).
//
// R12 (9.48ms, rel_err 0.0): quad-sum table T[q][idx][j] (32x16x128 fp32, L1-resident),
// smem nib exchange + PRMT extract + 5-FMA Taylor sigmoid. Issue 74.5% — single
// dependence stream per warp leaves scheduler idle during LDG scoreboard waits.
// R14: two samples per warp (GPW=2). Two independent chains interleave in the same
// loop body (ptxas keeps its own schedule, R13 lesson). Per-sample arithmetic is
// byte-identical to R12: same counters, same ascending-q add order, same sigmoid.

#define NSAMP    524288
#define LATENT   128
#define NSTEPS   30
#define GPW      2
#define WARPS_PB 8
#define THREADS_PB 256
#define NBLOCKS  (NSAMP / (GPW * WARPS_PB))   // 32768

#define TAB_ELEMS (32 * 16 * 128)       // 256 KB fp32
__device__ __align__(256) float g_qtable[TAB_ELEMS];

struct Keys { uint2 k[1 + NSTEPS]; };   // k[0] = z0 key, k[1+t] = step t key

__host__ __device__ __forceinline__ uint32_t rotl32(uint32_t x, int r) {
#ifdef __CUDA_ARCH__
    return __funnelshift_l(x, x, r);
#else
    return (x << r) | (x >> (32 - r));
#endif
}

// Threefry-2x32, 20 rounds (exactly JAX's threefry2x32).
__host__ __device__ __forceinline__ uint2 tf2x32(uint32_t k0, uint32_t k1,
                                                 uint32_t x0, uint32_t x1) {
    uint32_t k2 = k0 ^ k1 ^ 0x1BD11BDAu;
    x0 += k0; x1 += k1;
#define TFR(r) { x0 += x1; x1 = rotl32(x1, r); x1 ^= x0; }
    TFR(13) TFR(15) TFR(26) TFR(6)   x0 += k1; x1 += k2 + 1u;
    TFR(17) TFR(29) TFR(16) TFR(24)  x0 += k2; x1 += k0 + 2u;
    TFR(13) TFR(15) TFR(26) TFR(6)   x0 += k0; x1 += k1 + 3u;
    TFR(17) TFR(29) TFR(16) TFR(24)  x0 += k1; x1 += k2 + 4u;
    TFR(13) TFR(15) TFR(26) TFR(6)   x0 += k2; x1 += k0 + 5u;
#undef TFR
    return make_uint2(x0, x1);
}

// Partitionable-mode random bits: counter = (hi=0, lo=flat_index), xor lanes.
__device__ __forceinline__ uint32_t tf_bits(uint32_t k0, uint32_t k1, uint32_t ctr) {
    uint2 r = tf2x32(k0, k1, 0u, ctr);
    return r.x ^ r.y;
}

// Packed fp32 pair add (elementwise RN; base Blackwell ISA, fma pipe).
__device__ __forceinline__ uint64_t add2(uint64_t a, uint64_t b) {
    uint64_t r; asm("add.rn.f32x2 %0, %1, %2;" : "=l"(r) : "l"(a), "l"(b)); return r;
}
__device__ __forceinline__ uint64_t pack2(float a, float b) {
    uint64_t r; asm("mov.b64 %0, {%1, %2};" : "=l"(r) : "f"(a), "f"(b)); return r;
}
__device__ __forceinline__ float2 unpack2(uint64_t v) {
    float2 r; asm("mov.b64 {%0, %1}, %2;" : "=f"(r.x), "=f"(r.y) : "l"(v)); return r;
}

// ---- build the quad table: T[q][i][j] = sum_{b ascending, bit b of i} W[4q+b][j] ----
__global__ void build_qtable_kernel(const float* __restrict__ W) {
    int t = blockIdx.x * blockDim.x + threadIdx.x;   // 0 .. 65535
    int j = t & 127;
    int i = (t >> 7) & 15;
    int q = t >> 11;
    float acc = 0.0f;
#pragma unroll
    for (int b = 0; b < 4; b++)
        if ((i >> b) & 1) acc += W[(4 * q + b) * 128 + j];
    g_qtable[t] = acc;
}

// ---- main chain kernel: two samples per warp ----
__global__ __launch_bounds__(THREADS_PB)
void rbm_gibbs_kernel(const float* __restrict__ hvec,
                      float* __restrict__ out,
                      Keys keys) {
    // Double-buffered per-warp nib strips, one 32B strip per sample stream.
    __shared__ __align__(16) uint8_t nibbuf[WARPS_PB][2][GPW][32];

    const int lane = threadIdx.x & 31;
    const int wid  = threadIdx.x >> 5;
    const int sample0 = (blockIdx.x * WARPS_PB + wid) * GPW;

    uint32_t base[GPW];
#pragma unroll
    for (int g = 0; g < GPW; g++)
        base[g] = (uint32_t)(sample0 + g) * (uint32_t)LATENT + (uint32_t)(lane * 4);

    const float4 h4 = reinterpret_cast<const float4*>(hvec)[lane];
    const uint64_t h01 = pack2(h4.x, h4.y);
    const uint64_t h23 = pack2(h4.z, h4.w);

    // Table rows as packed pairs: row (q, idx) = 32 ulonglong2; lane reads entry 'lane'.
    const ulonglong2* __restrict__ tab =
        reinterpret_cast<const ulonglong2*>(g_qtable) + lane;

    // nib[g] = quad index for sample g: bit c = z_{4*lane+c}
    uint32_t nib[GPW];
    {
        const uint32_t ik0 = keys.k[0].x, ik1 = keys.k[0].y;
#pragma unroll
        for (int g = 0; g < GPW; g++) {
            nib[g] = 0u;
#pragma unroll
            for (int c = 0; c < 4; c++)
                nib[g] |= (tf_bits(ik0, ik1, base[g] + (uint32_t)c) & 1u) << c;
        }
    }

    for (int t = 0; t < NSTEPS; t++) {
        // ---- warp-wide nib exchange: GPW STS + 2*GPW broadcast LDS.128, one sync ----
#pragma unroll
        for (int g = 0; g < GPW; g++)
            nibbuf[wid][t & 1][g][lane] = (uint8_t)nib[g];
        __syncwarp();
        uint32_t r[GPW][8];
#pragma unroll
        for (int g = 0; g < GPW; g++) {
            const uint8_t* buf = nibbuf[wid][t & 1][g];
            const uint4 n0 = *reinterpret_cast<const uint4*>(&buf[0]);
            const uint4 n1 = *reinterpret_cast<const uint4*>(&buf[16]);
            r[g][0] = n0.x; r[g][1] = n0.y; r[g][2] = n0.z; r[g][3] = n0.w;
            r[g][4] = n1.x; r[g][5] = n1.y; r[g][6] = n1.z; r[g][7] = n1.w;
        }

        uint64_t y01[GPW], y23[GPW];
#pragma unroll
        for (int g = 0; g < GPW; g++) { y01[g] = h01; y23[g] = h23; }

        // y += sum over 32 quads of T[q][nib_q]; two independent streams interleaved.
#pragma unroll
        for (int q = 0; q < 32; q++) {
            const uint32_t sel = 0x4440u | (uint32_t)(q & 3);
#pragma unroll
            for (int g = 0; g < GPW; g++) {
                uint32_t nb = __byte_perm(r[g][q >> 2], 0u, sel);
                ulonglong2 w = __ldg(&tab[(uint32_t)(q * 512) + nb * 32u]);
                y01[g] = add2(y01[g], w.x);
                y23[g] = add2(y23[g], w.y);
            }
        }

        // sample: u = uniform(step_key), z' = (u < sigmoid(y)); sigmoid via odd
        // Taylor poly (|y| <= ~0.10, analytic err < 2e-14, byte-identical to R12).
        const uint32_t sk0 = keys.k[1 + t].x, sk1 = keys.k[1 + t].y;
#pragma unroll
        for (int g = 0; g < GPW; g++) {
            float2 ya = unpack2(y01[g]);
            float2 yc = unpack2(y23[g]);
            float yv[4] = { ya.x, ya.y, yc.x, yc.y };
            uint32_t nnew = 0u;
#pragma unroll
            for (int c = 0; c < 4; c++) {
                uint32_t b = tf_bits(sk0, sk1, base[g] + (uint32_t)c);
                float u = __uint_as_float((b >> 9) | 0x3f800000u) - 1.0f;
                float y2 = yv[c] * yv[c];
                float poly = fmaf(y2, fmaf(y2, fmaf(y2, -2.1081349e-4f, 2.0833333e-3f),
                                           -2.0833333e-2f), 0.25f);
                float p = fmaf(yv[c], poly, 0.5f);
                nnew |= (u < p ? 1u : 0u) << c;
            }
            nib[g] = nnew;
        }
    }

    // ---- write z_final (float32, row-major [NSAMP, 128]) ----
#pragma unroll
    for (int g = 0; g < GPW; g++) {
        float4 v = make_float4((nib[g] & 1u) ? 1.0f : 0.0f,
                               (nib[g] & 2u) ? 1.0f : 0.0f,
                               (nib[g] & 4u) ? 1.0f : 0.0f,
                               (nib[g] & 8u) ? 1.0f : 0.0f);
        reinterpret_cast<float4*>(out)[(size_t)(sample0 + g) * 32 + lane] = v;
    }
}

extern "C" void kernel_launch(void* const* d_in, const int* in_sizes, int n_in,
                              void* d_out, int out_size) {
    (void)in_sizes; (void)n_in; (void)out_size;
    const float* h = (const float*)d_in[0];
    const float* W = (const float*)d_in[1];
    float* out = (float*)d_out;

    // Host-side key schedule (pure CPU math; deterministic, capture-safe).
    Keys keys;
    uint2 kinit = tf2x32(0u, 42u, 0u, 0u);
    uint2 kloop = tf2x32(0u, 42u, 0u, 1u);
    keys.k[0] = kinit;
    for (int t = 0; t < NSTEPS; t++)
        keys.k[1 + t] = tf2x32(kloop.x, kloop.y, 0u, (uint32_t)t);

    // Same stream: table build completes before the chain kernel reads it.
    build_qtable_kernel<<<TAB_ELEMS / 256, 256>>>(W);
    rbm_gibbs_kernel<<<NBLOCKS, THREADS_PB>>>(h, out, keys);
}